// round 9
// baseline (speedup 1.0000x reference)
#include <cuda_runtime.h>
#include <cuda_bf16.h>
#include <math.h>

#define N_USERS 100000
#define N_ITEMS 50000
#define N_NODES (N_USERS + N_ITEMS)
#define DIM 32
#define N_EDGES 2400000
#define K_STEPS 10

#define SCAN_BLOCK 1024
#define SCAN_NBLOCKS ((N_NODES + SCAN_BLOCK - 1) / SCAN_BLOCK)   // 147 <= 148 SMs: all resident

// ---------------- device scratch (no allocations allowed) ----------------
__device__ float g_h[N_NODES * DIM];        // current state
__device__ float g_t[N_NODES * DIM];        // hop-1 result
__device__ float g_init[N_NODES * DIM];     // normalized static state
__device__ float g_alpha[N_NODES];          // sigmoid(alpha_logit)
__device__ int2  g_edges[N_EDGES];          // CSR payload: {src, w bits} grouped by dst
__device__ int   g_rowstart[N_NODES + 1];   // CSR row pointers (by dst)
__device__ int   g_cursor[N_NODES];         // counts, then scatter cursors
__device__ unsigned long long g_scan_desc[SCAN_NBLOCKS]; // (state<<32)|value; 1=aggregate,2=prefix
__device__ unsigned g_maxbits;              // max row sumsq (bit-compare trick)

// ---------------- 1. fused: zero counters + max row-norm^2 ----------------
__global__ void norm_zero_kernel(const float* __restrict__ xu, const float* __restrict__ xi) {
    int gid  = blockIdx.x * blockDim.x + threadIdx.x;
    if (gid < N_NODES) g_cursor[gid] = 0;
    if (gid < SCAN_NBLOCKS) g_scan_desc[gid] = 0ULL;
    if (gid == 0) g_maxbits = 0u;

    int warp = gid >> 5;
    int lane = threadIdx.x & 31;
    if (warp >= N_NODES) return;
    const float* row = (warp < N_USERS) ? (xu + (size_t)warp * DIM)
                                        : (xi + (size_t)(warp - N_USERS) * DIM);
    float v = row[lane];
    float ss = v * v;
    #pragma unroll
    for (int d = 16; d; d >>= 1) ss += __shfl_xor_sync(0xFFFFFFFFu, ss, d);
    if (lane == 0) atomicMax(&g_maxbits, __float_as_uint(ss));  // ss >= 0: bit order == float order
}

// ---------------- 2. histogram of edge_dst ----------------
__global__ void count_kernel(const int* __restrict__ edge_dst) {
    int e = blockIdx.x * blockDim.x + threadIdx.x;
    if (e < N_EDGES) atomicAdd(&g_cursor[edge_dst[e]], 1);
}

// ---------------- 3. single-pass scan (decoupled lookback, FIXED) ----------
// Writes g_rowstart (exclusive scan of counts) AND g_cursor (scatter cursors).
__global__ __launch_bounds__(SCAN_BLOCK) void scan_kernel() {
    __shared__ int warp_sums[32];
    __shared__ int s_prefix;
    int bid = blockIdx.x;
    int i = bid * SCAN_BLOCK + threadIdx.x;
    int lane = threadIdx.x & 31, wid = threadIdx.x >> 5;
    int v = (i < N_NODES) ? g_cursor[i] : 0;

    // block-local inclusive scan
    int x = v;
    #pragma unroll
    for (int d = 1; d < 32; d <<= 1) {
        int t = __shfl_up_sync(0xFFFFFFFFu, x, d);
        if (lane >= d) x += t;
    }
    if (lane == 31) warp_sums[wid] = x;
    __syncthreads();
    if (wid == 0) {
        int y = warp_sums[lane];
        #pragma unroll
        for (int d = 1; d < 32; d <<= 1) {
            int t = __shfl_up_sync(0xFFFFFFFFu, y, d);
            if (lane >= d) y += t;
        }
        warp_sums[lane] = y;
    }
    __syncthreads();
    int warp_excl = (wid == 0) ? 0 : warp_sums[wid - 1];
    int incl = warp_excl + x;                 // block-local inclusive
    int block_total = warp_sums[31];

    // publish: block 0 publishes prefix directly, others publish aggregate
    if (threadIdx.x == 0) {
        unsigned long long st = (bid == 0) ? 2ULL : 1ULL;
        atomicExch(&g_scan_desc[bid], (st << 32) | (unsigned)block_total);
    }

    if (threadIdx.x == 0) s_prefix = 0;
    __syncthreads();

    // decoupled lookback (warp 0). FIX vs previous round: when a 32-wide
    // window holds no published prefix (all aggregates), sum the WHOLE
    // window and keep looking back; previously those 32 aggregates were
    // silently dropped (firstp = -1), corrupting the scan.
    if (bid > 0 && wid == 0) {
        int running = 0;
        int look = bid - 1;
        while (true) {
            int idx = look - lane;            // lane 0 = closest predecessor
            unsigned long long d = 0;
            if (idx >= 0) {
                do {
                    d = *(volatile unsigned long long*)&g_scan_desc[idx];
                } while ((d >> 32) == 0ULL);
            }
            int st  = (idx >= 0) ? (int)(d >> 32) : 2;      // oob acts as prefix 0
            int val = (idx >= 0) ? (int)(unsigned)d : 0;
            unsigned pmask = __ballot_sync(0xFFFFFFFFu, st == 2);
            int firstp = pmask ? (__ffs(pmask) - 1) : 31;   // no prefix: take whole window
            int contrib = (lane <= firstp) ? val : 0;
            #pragma unroll
            for (int dd = 16; dd; dd >>= 1) contrib += __shfl_xor_sync(0xFFFFFFFFu, contrib, dd);
            running += contrib;
            if (pmask) { if (lane == 0) s_prefix = running; break; }
            look -= 32;
        }
        __syncwarp();
    }
    __syncthreads();
    int prefix = s_prefix;

    // upgrade our descriptor to inclusive prefix so successors stop here
    if (bid > 0 && threadIdx.x == 0) {
        atomicExch(&g_scan_desc[bid], (2ULL << 32) | (unsigned)(prefix + block_total));
    }

    int excl = prefix + incl - v;
    if (i < N_NODES) {
        g_rowstart[i] = excl;
        g_cursor[i]   = excl;
    }
    if (bid == SCAN_NBLOCKS - 1 && threadIdx.x == SCAN_BLOCK - 1) {
        g_rowstart[N_NODES] = prefix + block_total;
    }
}

// ---------------- 4. scatter edges into CSR buckets ----------------
__global__ void scatter_kernel(const int* __restrict__ edge_src,
                               const int* __restrict__ edge_dst,
                               const float* __restrict__ edge_w) {
    int e = blockIdx.x * blockDim.x + threadIdx.x;
    if (e >= N_EDGES) return;
    int dst = edge_dst[e];
    int p = atomicAdd(&g_cursor[dst], 1);
    g_edges[p] = make_int2(edge_src[e], __float_as_int(edge_w[e]));
}

// ---------------- 5. normalize state / static, sigmoid alpha ----------------
__global__ void init_kernel(const float* __restrict__ xu, const float* __restrict__ xi,
                            const float* __restrict__ su, const float* __restrict__ si,
                            const float* __restrict__ alpha_logit) {
    int idx = blockIdx.x * blockDim.x + threadIdx.x;
    if (idx < N_NODES * DIM) {
        float scale = rsqrtf(__uint_as_float(g_maxbits));
        float s, st;
        if (idx < N_USERS * DIM) { s = xu[idx]; st = su[idx]; }
        else                     { s = xi[idx - N_USERS * DIM]; st = si[idx - N_USERS * DIM]; }
        g_h[idx]    = s  * scale;
        g_init[idx] = st * scale;
    }
    if (idx < N_NODES) {
        g_alpha[idx] = 1.0f / (1.0f + expf(-alpha_logit[idx]));
    }
}

// ---------------- 6. propagation hop (EXACT R2 kernel: proven 876us) -------
template <bool UPDATE>
__global__ void hop_kernel(const float2* __restrict__ in, float2* __restrict__ out,
                           const float* __restrict__ dt) {
    int t = blockIdx.x * blockDim.x + threadIdx.x;
    int node = t >> 4;            // half-warp per node
    int sub  = t & 15;            // float2 slot within the 32-dim row
    if (node >= N_NODES) return;
    int s = __ldg(&g_rowstart[node]);
    int e = __ldg(&g_rowstart[node + 1]);

    float ax0 = 0.f, ay0 = 0.f, ax1 = 0.f, ay1 = 0.f;
    int k = s;
    for (; k + 1 < e; k += 2) {
        int2 e0 = __ldg(&g_edges[k]);
        int2 e1 = __ldg(&g_edges[k + 1]);
        float2 v0 = __ldg(&in[e0.x * (DIM / 2) + sub]);
        float2 v1 = __ldg(&in[e1.x * (DIM / 2) + sub]);
        float w0 = __int_as_float(e0.y);
        float w1 = __int_as_float(e1.y);
        ax0 = fmaf(w0, v0.x, ax0); ay0 = fmaf(w0, v0.y, ay0);
        ax1 = fmaf(w1, v1.x, ax1); ay1 = fmaf(w1, v1.y, ay1);
    }
    if (k < e) {
        int2 e0 = __ldg(&g_edges[k]);
        float2 v0 = __ldg(&in[e0.x * (DIM / 2) + sub]);
        float w0 = __int_as_float(e0.y);
        ax0 = fmaf(w0, v0.x, ax0); ay0 = fmaf(w0, v0.y, ay0);
    }
    float accx = ax0 + ax1, accy = ay0 + ay1;

    int oidx = node * (DIM / 2) + sub;
    if (UPDATE) {
        float step = __ldg(dt) * (1.0f / K_STEPS);
        float2 h   = ((const float2*)g_h)[oidx];
        float2 ini = ((const float2*)g_init)[oidx];
        float a    = __ldg(&g_alpha[node]);
        float2 r;
        r.x = h.x + step * (accx - a * h.x + ini.x);
        r.y = h.y + step * (accy - a * h.y + ini.y);
        out[oidx] = r;
    } else {
        float2 r; r.x = accx; r.y = accy;
        out[oidx] = r;
    }
}

// ---------------- launch ----------------
extern "C" void kernel_launch(void* const* d_in, const int* in_sizes, int n_in,
                              void* d_out, int out_size) {
    const float* xu          = (const float*)d_in[0];
    const float* xi          = (const float*)d_in[1];
    const float* su          = (const float*)d_in[2];
    const float* si          = (const float*)d_in[3];
    const float* edge_w      = (const float*)d_in[4];
    const float* alpha_logit = (const float*)d_in[5];
    const float* dt          = (const float*)d_in[6];
    const int*   edge_src    = (const int*)d_in[7];
    const int*   edge_dst    = (const int*)d_in[8];
    float*       out         = (float*)d_out;

    const int T = 256;
    const int warpNodeBlocks = (N_NODES * 32 + T - 1) / T;
    const int halfNodeBlocks = (N_NODES * 16 + T - 1) / T;
    const int edgeBlocks     = (N_EDGES + T - 1) / T;
    const int elemBlocks     = (N_NODES * DIM + T - 1) / T;

    // 5 launches before the first hop -> ncu (-s 5 -c 1) captures hop_kernel
    norm_zero_kernel<<<warpNodeBlocks, T>>>(xu, xi);                  // 1
    count_kernel<<<edgeBlocks, T>>>(edge_dst);                        // 2
    scan_kernel<<<SCAN_NBLOCKS, SCAN_BLOCK>>>();                      // 3
    scatter_kernel<<<edgeBlocks, T>>>(edge_src, edge_dst, edge_w);    // 4
    init_kernel<<<elemBlocks, T>>>(xu, xi, su, si, alpha_logit);      // 5

    void* p_h = nullptr; void* p_t = nullptr;
    cudaGetSymbolAddress(&p_h, g_h);
    cudaGetSymbolAddress(&p_t, g_t);
    float2* fh = (float2*)p_h;
    float2* ft = (float2*)p_t;

    for (int step = 0; step < K_STEPS; step++) {
        hop_kernel<false><<<halfNodeBlocks, T>>>(fh, ft, dt);
        float2* dst2 = (step == K_STEPS - 1) ? (float2*)out : fh;
        hop_kernel<true><<<halfNodeBlocks, T>>>(ft, dst2, dt);
    }
}

// round 10
// speedup vs baseline: 1.6176x; 1.6176x over previous
#include <cuda_runtime.h>
#include <cuda_bf16.h>
#include <cuda_fp16.h>
#include <math.h>

#define N_USERS 100000
#define N_ITEMS 50000
#define N_NODES (N_USERS + N_ITEMS)
#define DIM 32
#define N_EDGES 2400000
#define K_STEPS 10

#define SCAN_BLOCK 1024
#define SCAN_NBLOCKS ((N_NODES + SCAN_BLOCK - 1) / SCAN_BLOCK)   // 147 <= 148 SMs: all resident

// ---------------- device scratch (no allocations allowed) ----------------
__device__ float   g_h[N_NODES * DIM];        // fp32 state
__device__ __half2 g_h16[N_NODES * (DIM/2)];  // fp16 shadow of state (gather operand)
__device__ __half2 g_t16[N_NODES * (DIM/2)];  // hop-1 result, fp16 only
__device__ float   g_init[N_NODES * DIM];     // normalized static state
__device__ float   g_alpha[N_NODES];          // sigmoid(alpha_logit)
__device__ int2    g_edges[N_EDGES];          // CSR payload {src, w bits} grouped by dst
__device__ int     g_rowstart[N_NODES + 1];   // CSR row pointers (by dst)
__device__ int     g_cursor[N_NODES];         // counts, then scatter cursors
__device__ unsigned long long g_scan_desc[SCAN_NBLOCKS]; // (state<<32)|value; 1=agg,2=prefix
__device__ unsigned g_maxbits;                // max row sumsq (bit-compare trick)

// ---------------- 1. fused: zero counters + max row-norm^2 ----------------
__global__ void norm_zero_kernel(const float* __restrict__ xu, const float* __restrict__ xi) {
    int gid  = blockIdx.x * blockDim.x + threadIdx.x;
    if (gid < N_NODES) g_cursor[gid] = 0;
    if (gid < SCAN_NBLOCKS) g_scan_desc[gid] = 0ULL;
    if (gid == 0) g_maxbits = 0u;

    int warp = gid >> 5;
    int lane = threadIdx.x & 31;
    if (warp >= N_NODES) return;
    const float* row = (warp < N_USERS) ? (xu + (size_t)warp * DIM)
                                        : (xi + (size_t)(warp - N_USERS) * DIM);
    float v = row[lane];
    float ss = v * v;
    #pragma unroll
    for (int d = 16; d; d >>= 1) ss += __shfl_xor_sync(0xFFFFFFFFu, ss, d);
    if (lane == 0) atomicMax(&g_maxbits, __float_as_uint(ss));  // ss >= 0: bit order == float order
}

// ---------------- 2. histogram of edge_dst ----------------
__global__ void count_kernel(const int* __restrict__ edge_dst) {
    int e = blockIdx.x * blockDim.x + threadIdx.x;
    if (e < N_EDGES) atomicAdd(&g_cursor[edge_dst[e]], 1);
}

// ---------------- 3. single-pass scan (decoupled lookback; proven R8) ------
__global__ __launch_bounds__(SCAN_BLOCK) void scan_kernel() {
    __shared__ int warp_sums[32];
    __shared__ int s_prefix;
    int bid = blockIdx.x;
    int i = bid * SCAN_BLOCK + threadIdx.x;
    int lane = threadIdx.x & 31, wid = threadIdx.x >> 5;
    int v = (i < N_NODES) ? g_cursor[i] : 0;

    int x = v;
    #pragma unroll
    for (int d = 1; d < 32; d <<= 1) {
        int t = __shfl_up_sync(0xFFFFFFFFu, x, d);
        if (lane >= d) x += t;
    }
    if (lane == 31) warp_sums[wid] = x;
    __syncthreads();
    if (wid == 0) {
        int y = warp_sums[lane];
        #pragma unroll
        for (int d = 1; d < 32; d <<= 1) {
            int t = __shfl_up_sync(0xFFFFFFFFu, y, d);
            if (lane >= d) y += t;
        }
        warp_sums[lane] = y;
    }
    __syncthreads();
    int warp_excl = (wid == 0) ? 0 : warp_sums[wid - 1];
    int incl = warp_excl + x;
    int block_total = warp_sums[31];

    if (threadIdx.x == 0) {
        unsigned long long st = (bid == 0) ? 2ULL : 1ULL;
        atomicExch(&g_scan_desc[bid], (st << 32) | (unsigned)block_total);
    }
    if (threadIdx.x == 0) s_prefix = 0;
    __syncthreads();

    if (bid > 0 && wid == 0) {
        int running = 0;
        int look = bid - 1;
        while (true) {
            int idx = look - lane;
            unsigned long long d = 0;
            if (idx >= 0) {
                do { d = *(volatile unsigned long long*)&g_scan_desc[idx]; }
                while ((d >> 32) == 0ULL);
            }
            int st  = (idx >= 0) ? (int)(d >> 32) : 2;
            int val = (idx >= 0) ? (int)(unsigned)d : 0;
            unsigned pmask = __ballot_sync(0xFFFFFFFFu, st == 2);
            int firstp = pmask ? (__ffs(pmask) - 1) : 31;  // no prefix: take whole window
            int contrib = (lane <= firstp) ? val : 0;
            #pragma unroll
            for (int dd = 16; dd; dd >>= 1) contrib += __shfl_xor_sync(0xFFFFFFFFu, contrib, dd);
            running += contrib;
            if (pmask) { if (lane == 0) s_prefix = running; break; }
            look -= 32;
        }
        __syncwarp();
    }
    __syncthreads();
    int prefix = s_prefix;

    if (bid > 0 && threadIdx.x == 0) {
        atomicExch(&g_scan_desc[bid], (2ULL << 32) | (unsigned)(prefix + block_total));
    }

    int excl = prefix + incl - v;
    if (i < N_NODES) {
        g_rowstart[i] = excl;
        g_cursor[i]   = excl;
    }
    if (bid == SCAN_NBLOCKS - 1 && threadIdx.x == SCAN_BLOCK - 1) {
        g_rowstart[N_NODES] = prefix + block_total;
    }
}

// ---------------- 4. scatter edges into CSR buckets ----------------
__global__ void scatter_kernel(const int* __restrict__ edge_src,
                               const int* __restrict__ edge_dst,
                               const float* __restrict__ edge_w) {
    int e = blockIdx.x * blockDim.x + threadIdx.x;
    if (e >= N_EDGES) return;
    int dst = edge_dst[e];
    int p = atomicAdd(&g_cursor[dst], 1);
    g_edges[p] = make_int2(edge_src[e], __float_as_int(edge_w[e]));
}

// ---------------- 5. normalize + build fp32 state, fp16 shadow, alpha ------
// One thread per element-pair: writes g_h (float2), g_h16 (half2), g_init (float2).
__global__ void init_kernel(const float* __restrict__ xu, const float* __restrict__ xi,
                            const float* __restrict__ su, const float* __restrict__ si,
                            const float* __restrict__ alpha_logit) {
    int p = blockIdx.x * blockDim.x + threadIdx.x;   // pair index
    if (p < N_NODES * (DIM / 2)) {
        float scale = rsqrtf(__uint_as_float(g_maxbits));
        int i0 = p * 2;
        float s0, s1, t0, t1;
        if (i0 < N_USERS * DIM) {
            s0 = xu[i0]; s1 = xu[i0 + 1]; t0 = su[i0]; t1 = su[i0 + 1];
        } else {
            int j = i0 - N_USERS * DIM;
            s0 = xi[j]; s1 = xi[j + 1]; t0 = si[j]; t1 = si[j + 1];
        }
        float h0 = s0 * scale, h1 = s1 * scale;
        ((float2*)g_h)[p]    = make_float2(h0, h1);
        ((float2*)g_init)[p] = make_float2(t0 * scale, t1 * scale);
        g_h16[p] = __floats2half2_rn(h0, h1);
    }
    if (p < N_NODES) {
        g_alpha[p] = 1.0f / (1.0f + expf(-alpha_logit[p]));
    }
}

// ---------------- 6a. hop 1: gather fp16, write fp16 intermediate ----------
// Half-warp per node (natural order), half2 per lane — 64B per row gather.
__global__ void hop1_kernel(const __half2* __restrict__ in, __half2* __restrict__ out) {
    int t = blockIdx.x * blockDim.x + threadIdx.x;
    int node = t >> 4;
    int sub  = t & 15;
    if (node >= N_NODES) return;
    int s = __ldg(&g_rowstart[node]);
    int e = __ldg(&g_rowstart[node + 1]);

    float ax0 = 0.f, ay0 = 0.f, ax1 = 0.f, ay1 = 0.f;
    int k = s;
    for (; k + 1 < e; k += 2) {
        int2 e0 = __ldg(&g_edges[k]);
        int2 e1 = __ldg(&g_edges[k + 1]);
        float2 v0 = __half22float2(__ldg(&in[e0.x * (DIM / 2) + sub]));
        float2 v1 = __half22float2(__ldg(&in[e1.x * (DIM / 2) + sub]));
        float w0 = __int_as_float(e0.y);
        float w1 = __int_as_float(e1.y);
        ax0 = fmaf(w0, v0.x, ax0); ay0 = fmaf(w0, v0.y, ay0);
        ax1 = fmaf(w1, v1.x, ax1); ay1 = fmaf(w1, v1.y, ay1);
    }
    if (k < e) {
        int2 e0 = __ldg(&g_edges[k]);
        float2 v0 = __half22float2(__ldg(&in[e0.x * (DIM / 2) + sub]));
        float w0 = __int_as_float(e0.y);
        ax0 = fmaf(w0, v0.x, ax0); ay0 = fmaf(w0, v0.y, ay0);
    }
    out[node * (DIM / 2) + sub] = __floats2half2_rn(ax0 + ax1, ay0 + ay1);
}

// ---------------- 6b. hop 2 + Euler update ---------------------------------
// Gathers fp16 intermediate, fp32 update; writes fp32 state (or d_out) and,
// unless LAST, refreshes the fp16 shadow for the next step's hop 1.
template <bool LAST>
__global__ void hop2_kernel(const __half2* __restrict__ in, float2* __restrict__ out,
                            const float* __restrict__ dt) {
    int t = blockIdx.x * blockDim.x + threadIdx.x;
    int node = t >> 4;
    int sub  = t & 15;
    if (node >= N_NODES) return;
    int s = __ldg(&g_rowstart[node]);
    int e = __ldg(&g_rowstart[node + 1]);

    float ax0 = 0.f, ay0 = 0.f, ax1 = 0.f, ay1 = 0.f;
    int k = s;
    for (; k + 1 < e; k += 2) {
        int2 e0 = __ldg(&g_edges[k]);
        int2 e1 = __ldg(&g_edges[k + 1]);
        float2 v0 = __half22float2(__ldg(&in[e0.x * (DIM / 2) + sub]));
        float2 v1 = __half22float2(__ldg(&in[e1.x * (DIM / 2) + sub]));
        float w0 = __int_as_float(e0.y);
        float w1 = __int_as_float(e1.y);
        ax0 = fmaf(w0, v0.x, ax0); ay0 = fmaf(w0, v0.y, ay0);
        ax1 = fmaf(w1, v1.x, ax1); ay1 = fmaf(w1, v1.y, ay1);
    }
    if (k < e) {
        int2 e0 = __ldg(&g_edges[k]);
        float2 v0 = __half22float2(__ldg(&in[e0.x * (DIM / 2) + sub]));
        float w0 = __int_as_float(e0.y);
        ax0 = fmaf(w0, v0.x, ax0); ay0 = fmaf(w0, v0.y, ay0);
    }
    float accx = ax0 + ax1, accy = ay0 + ay1;

    int oidx = node * (DIM / 2) + sub;
    float step = __ldg(dt) * (1.0f / K_STEPS);
    float2 h   = ((const float2*)g_h)[oidx];
    float2 ini = ((const float2*)g_init)[oidx];
    float a    = __ldg(&g_alpha[node]);
    float2 r;
    r.x = h.x + step * (accx - a * h.x + ini.x);
    r.y = h.y + step * (accy - a * h.y + ini.y);
    out[oidx] = r;
    if (!LAST) {
        g_h16[oidx] = __floats2half2_rn(r.x, r.y);
    }
}

// ---------------- launch ----------------
extern "C" void kernel_launch(void* const* d_in, const int* in_sizes, int n_in,
                              void* d_out, int out_size) {
    const float* xu          = (const float*)d_in[0];
    const float* xi          = (const float*)d_in[1];
    const float* su          = (const float*)d_in[2];
    const float* si          = (const float*)d_in[3];
    const float* edge_w      = (const float*)d_in[4];
    const float* alpha_logit = (const float*)d_in[5];
    const float* dt          = (const float*)d_in[6];
    const int*   edge_src    = (const int*)d_in[7];
    const int*   edge_dst    = (const int*)d_in[8];
    float*       out         = (float*)d_out;

    const int T = 256;
    const int warpNodeBlocks = (N_NODES * 32 + T - 1) / T;
    const int halfNodeBlocks = (N_NODES * 16 + T - 1) / T;
    const int edgeBlocks     = (N_EDGES + T - 1) / T;
    const int pairBlocks     = (N_NODES * (DIM / 2) + T - 1) / T;

    norm_zero_kernel<<<warpNodeBlocks, T>>>(xu, xi);                  // 1
    count_kernel<<<edgeBlocks, T>>>(edge_dst);                        // 2
    scan_kernel<<<SCAN_NBLOCKS, SCAN_BLOCK>>>();                      // 3
    scatter_kernel<<<edgeBlocks, T>>>(edge_src, edge_dst, edge_w);    // 4
    init_kernel<<<pairBlocks, T>>>(xu, xi, su, si, alpha_logit);      // 5

    void* p_h16 = nullptr; void* p_t16 = nullptr; void* p_h = nullptr;
    cudaGetSymbolAddress(&p_h16, g_h16);
    cudaGetSymbolAddress(&p_t16, g_t16);
    cudaGetSymbolAddress(&p_h,   g_h);
    __half2* fh16 = (__half2*)p_h16;
    __half2* ft16 = (__half2*)p_t16;
    float2*  fh   = (float2*)p_h;

    for (int step = 0; step < K_STEPS; step++) {
        hop1_kernel<<<halfNodeBlocks, T>>>(fh16, ft16);
        if (step == K_STEPS - 1) {
            hop2_kernel<true><<<halfNodeBlocks, T>>>(ft16, (float2*)out, dt);
        } else {
            hop2_kernel<false><<<halfNodeBlocks, T>>>(ft16, fh, dt);
        }
    }
}

// round 11
// speedup vs baseline: 1.7858x; 1.1040x over previous
#include <cuda_runtime.h>
#include <cuda_bf16.h>
#include <cuda_fp16.h>
#include <math.h>

#define N_USERS 100000
#define N_ITEMS 50000
#define N_NODES (N_USERS + N_ITEMS)
#define DIM 32
#define N_EDGES 2400000
#define K_STEPS 10

#define SCAN_BLOCK 1024
#define SCAN_NBLOCKS ((N_NODES + SCAN_BLOCK - 1) / SCAN_BLOCK)   // 147 <= 148 SMs: all resident

// ---------------- device scratch (no allocations allowed) ----------------
__device__ float   g_h[N_NODES * DIM];        // fp32 state
__device__ __half2 g_h16[N_NODES * (DIM/2)];  // fp16 shadow of state (gather operand)
__device__ __half2 g_t16[N_NODES * (DIM/2)];  // hop-1 result, fp16 only
__device__ float   g_init[N_NODES * DIM];     // normalized static state
__device__ float   g_alpha[N_NODES];          // sigmoid(alpha_logit)
__device__ int2    g_edges[N_EDGES];          // CSR payload {src, w bits} grouped by dst
__device__ int     g_rowstart[N_NODES + 1];   // CSR row pointers (by dst)
__device__ int     g_cursor[N_NODES];         // counts, then scatter cursors
__device__ unsigned long long g_scan_desc[SCAN_NBLOCKS]; // (state<<32)|value; 1=agg,2=prefix
__device__ unsigned g_maxbits;                // max row sumsq (bit-compare trick)

// ---------------- 1. fused: zero counters + max row-norm^2 ----------------
__global__ void norm_zero_kernel(const float* __restrict__ xu, const float* __restrict__ xi) {
    int gid  = blockIdx.x * blockDim.x + threadIdx.x;
    if (gid < N_NODES) g_cursor[gid] = 0;
    if (gid < SCAN_NBLOCKS) g_scan_desc[gid] = 0ULL;
    if (gid == 0) g_maxbits = 0u;

    int warp = gid >> 5;
    int lane = threadIdx.x & 31;
    if (warp >= N_NODES) return;
    const float* row = (warp < N_USERS) ? (xu + (size_t)warp * DIM)
                                        : (xi + (size_t)(warp - N_USERS) * DIM);
    float v = row[lane];
    float ss = v * v;
    #pragma unroll
    for (int d = 16; d; d >>= 1) ss += __shfl_xor_sync(0xFFFFFFFFu, ss, d);
    if (lane == 0) atomicMax(&g_maxbits, __float_as_uint(ss));  // ss >= 0: bit order == float order
}

// ---------------- 2. histogram of edge_dst ----------------
__global__ void count_kernel(const int* __restrict__ edge_dst) {
    int e = blockIdx.x * blockDim.x + threadIdx.x;
    if (e < N_EDGES) atomicAdd(&g_cursor[edge_dst[e]], 1);
}

// ---------------- 3. single-pass scan (decoupled lookback; proven) ---------
__global__ __launch_bounds__(SCAN_BLOCK) void scan_kernel() {
    __shared__ int warp_sums[32];
    __shared__ int s_prefix;
    int bid = blockIdx.x;
    int i = bid * SCAN_BLOCK + threadIdx.x;
    int lane = threadIdx.x & 31, wid = threadIdx.x >> 5;
    int v = (i < N_NODES) ? g_cursor[i] : 0;

    int x = v;
    #pragma unroll
    for (int d = 1; d < 32; d <<= 1) {
        int t = __shfl_up_sync(0xFFFFFFFFu, x, d);
        if (lane >= d) x += t;
    }
    if (lane == 31) warp_sums[wid] = x;
    __syncthreads();
    if (wid == 0) {
        int y = warp_sums[lane];
        #pragma unroll
        for (int d = 1; d < 32; d <<= 1) {
            int t = __shfl_up_sync(0xFFFFFFFFu, y, d);
            if (lane >= d) y += t;
        }
        warp_sums[lane] = y;
    }
    __syncthreads();
    int warp_excl = (wid == 0) ? 0 : warp_sums[wid - 1];
    int incl = warp_excl + x;
    int block_total = warp_sums[31];

    if (threadIdx.x == 0) {
        unsigned long long st = (bid == 0) ? 2ULL : 1ULL;
        atomicExch(&g_scan_desc[bid], (st << 32) | (unsigned)block_total);
    }
    if (threadIdx.x == 0) s_prefix = 0;
    __syncthreads();

    if (bid > 0 && wid == 0) {
        int running = 0;
        int look = bid - 1;
        while (true) {
            int idx = look - lane;
            unsigned long long d = 0;
            if (idx >= 0) {
                do { d = *(volatile unsigned long long*)&g_scan_desc[idx]; }
                while ((d >> 32) == 0ULL);
            }
            int st  = (idx >= 0) ? (int)(d >> 32) : 2;
            int val = (idx >= 0) ? (int)(unsigned)d : 0;
            unsigned pmask = __ballot_sync(0xFFFFFFFFu, st == 2);
            int firstp = pmask ? (__ffs(pmask) - 1) : 31;  // no prefix: take whole window
            int contrib = (lane <= firstp) ? val : 0;
            #pragma unroll
            for (int dd = 16; dd; dd >>= 1) contrib += __shfl_xor_sync(0xFFFFFFFFu, contrib, dd);
            running += contrib;
            if (pmask) { if (lane == 0) s_prefix = running; break; }
            look -= 32;
        }
        __syncwarp();
    }
    __syncthreads();
    int prefix = s_prefix;

    if (bid > 0 && threadIdx.x == 0) {
        atomicExch(&g_scan_desc[bid], (2ULL << 32) | (unsigned)(prefix + block_total));
    }

    int excl = prefix + incl - v;
    if (i < N_NODES) {
        g_rowstart[i] = excl;
        g_cursor[i]   = excl;
    }
    if (bid == SCAN_NBLOCKS - 1 && threadIdx.x == SCAN_BLOCK - 1) {
        g_rowstart[N_NODES] = prefix + block_total;
    }
}

// ---------------- 4. scatter edges into CSR buckets ----------------
__global__ void scatter_kernel(const int* __restrict__ edge_src,
                               const int* __restrict__ edge_dst,
                               const float* __restrict__ edge_w) {
    int e = blockIdx.x * blockDim.x + threadIdx.x;
    if (e >= N_EDGES) return;
    int dst = edge_dst[e];
    int p = atomicAdd(&g_cursor[dst], 1);
    g_edges[p] = make_int2(edge_src[e], __float_as_int(edge_w[e]));
}

// ---------------- 5. normalize + build fp32 state, fp16 shadow, alpha ------
__global__ void init_kernel(const float* __restrict__ xu, const float* __restrict__ xi,
                            const float* __restrict__ su, const float* __restrict__ si,
                            const float* __restrict__ alpha_logit) {
    int p = blockIdx.x * blockDim.x + threadIdx.x;   // pair index
    if (p < N_NODES * (DIM / 2)) {
        float scale = rsqrtf(__uint_as_float(g_maxbits));
        int i0 = p * 2;
        float s0, s1, t0, t1;
        if (i0 < N_USERS * DIM) {
            s0 = xu[i0]; s1 = xu[i0 + 1]; t0 = su[i0]; t1 = su[i0 + 1];
        } else {
            int j = i0 - N_USERS * DIM;
            s0 = xi[j]; s1 = xi[j + 1]; t0 = si[j]; t1 = si[j + 1];
        }
        float h0 = s0 * scale, h1 = s1 * scale;
        ((float2*)g_h)[p]    = make_float2(h0, h1);
        ((float2*)g_init)[p] = make_float2(t0 * scale, t1 * scale);
        g_h16[p] = __floats2half2_rn(h0, h1);
    }
    if (p < N_NODES) {
        g_alpha[p] = 1.0f / (1.0f + expf(-alpha_logit[p]));
    }
}

// helpers: reinterpret uint as half2
__device__ __forceinline__ float2 u2f2(unsigned u) {
    __half2 h = *reinterpret_cast<__half2*>(&u);
    return __half22float2(h);
}
__device__ __forceinline__ unsigned f2u2(float a, float b) {
    __half2 h = __floats2half2_rn(a, b);
    return *reinterpret_cast<unsigned*>(&h);
}

// ---------------- 6a. hop 1: quarter-warp per node, uint2 (4 halfs)/lane ---
// One gather LDG instruction serves 4 edges (one per quarter-warp); one edge
// LDG serves 4 quarters. Halves the warp-level LDG issue count vs half-warp.
__global__ void hop1_kernel(const uint2* __restrict__ in, uint2* __restrict__ out) {
    int t = blockIdx.x * blockDim.x + threadIdx.x;
    int node = t >> 3;            // quarter-warp per node
    int l    = t & 7;             // uint2 slot: dims [4l, 4l+4)
    if (node >= N_NODES) return;
    int s = __ldg(&g_rowstart[node]);
    int e = __ldg(&g_rowstart[node + 1]);

    float ax0=0.f, ay0=0.f, az0=0.f, aw0=0.f;
    float ax1=0.f, ay1=0.f, az1=0.f, aw1=0.f;
    int k = s;
    for (; k + 1 < e; k += 2) {
        int2 e0 = __ldg(&g_edges[k]);
        int2 e1 = __ldg(&g_edges[k + 1]);
        uint2 r0 = __ldg(&in[e0.x * 8 + l]);
        uint2 r1 = __ldg(&in[e1.x * 8 + l]);
        float w0 = __int_as_float(e0.y);
        float w1 = __int_as_float(e1.y);
        float2 p00 = u2f2(r0.x), p01 = u2f2(r0.y);
        float2 p10 = u2f2(r1.x), p11 = u2f2(r1.y);
        ax0 = fmaf(w0, p00.x, ax0); ay0 = fmaf(w0, p00.y, ay0);
        az0 = fmaf(w0, p01.x, az0); aw0 = fmaf(w0, p01.y, aw0);
        ax1 = fmaf(w1, p10.x, ax1); ay1 = fmaf(w1, p10.y, ay1);
        az1 = fmaf(w1, p11.x, az1); aw1 = fmaf(w1, p11.y, aw1);
    }
    if (k < e) {
        int2 e0 = __ldg(&g_edges[k]);
        uint2 r0 = __ldg(&in[e0.x * 8 + l]);
        float w0 = __int_as_float(e0.y);
        float2 p00 = u2f2(r0.x), p01 = u2f2(r0.y);
        ax0 = fmaf(w0, p00.x, ax0); ay0 = fmaf(w0, p00.y, ay0);
        az0 = fmaf(w0, p01.x, az0); aw0 = fmaf(w0, p01.y, aw0);
    }
    out[node * 8 + l] = make_uint2(f2u2(ax0 + ax1, ay0 + ay1),
                                   f2u2(az0 + az1, aw0 + aw1));
}

// ---------------- 6b. hop 2 + Euler update (float4 state path) -------------
template <bool LAST>
__global__ void hop2_kernel(const uint2* __restrict__ in, float4* __restrict__ out,
                            const float* __restrict__ dt) {
    int t = blockIdx.x * blockDim.x + threadIdx.x;
    int node = t >> 3;
    int l    = t & 7;
    if (node >= N_NODES) return;
    int s = __ldg(&g_rowstart[node]);
    int e = __ldg(&g_rowstart[node + 1]);

    float ax0=0.f, ay0=0.f, az0=0.f, aw0=0.f;
    float ax1=0.f, ay1=0.f, az1=0.f, aw1=0.f;
    int k = s;
    for (; k + 1 < e; k += 2) {
        int2 e0 = __ldg(&g_edges[k]);
        int2 e1 = __ldg(&g_edges[k + 1]);
        uint2 r0 = __ldg(&in[e0.x * 8 + l]);
        uint2 r1 = __ldg(&in[e1.x * 8 + l]);
        float w0 = __int_as_float(e0.y);
        float w1 = __int_as_float(e1.y);
        float2 p00 = u2f2(r0.x), p01 = u2f2(r0.y);
        float2 p10 = u2f2(r1.x), p11 = u2f2(r1.y);
        ax0 = fmaf(w0, p00.x, ax0); ay0 = fmaf(w0, p00.y, ay0);
        az0 = fmaf(w0, p01.x, az0); aw0 = fmaf(w0, p01.y, aw0);
        ax1 = fmaf(w1, p10.x, ax1); ay1 = fmaf(w1, p10.y, ay1);
        az1 = fmaf(w1, p11.x, az1); aw1 = fmaf(w1, p11.y, aw1);
    }
    if (k < e) {
        int2 e0 = __ldg(&g_edges[k]);
        uint2 r0 = __ldg(&in[e0.x * 8 + l]);
        float w0 = __int_as_float(e0.y);
        float2 p00 = u2f2(r0.x), p01 = u2f2(r0.y);
        ax0 = fmaf(w0, p00.x, ax0); ay0 = fmaf(w0, p00.y, ay0);
        az0 = fmaf(w0, p01.x, az0); aw0 = fmaf(w0, p01.y, aw0);
    }
    float a0 = ax0 + ax1, a1 = ay0 + ay1, a2 = az0 + az1, a3 = aw0 + aw1;

    int oidx = node * 8 + l;                        // float4 index
    float step = __ldg(dt) * (1.0f / K_STEPS);
    float4 h   = ((const float4*)g_h)[oidx];
    float4 ini = ((const float4*)g_init)[oidx];
    float al   = __ldg(&g_alpha[node]);
    float4 r;
    r.x = h.x + step * (a0 - al * h.x + ini.x);
    r.y = h.y + step * (a1 - al * h.y + ini.y);
    r.z = h.z + step * (a2 - al * h.z + ini.z);
    r.w = h.w + step * (a3 - al * h.w + ini.w);
    out[oidx] = r;
    if (!LAST) {
        ((uint2*)g_h16)[oidx] = make_uint2(f2u2(r.x, r.y), f2u2(r.z, r.w));
    }
}

// ---------------- launch ----------------
extern "C" void kernel_launch(void* const* d_in, const int* in_sizes, int n_in,
                              void* d_out, int out_size) {
    const float* xu          = (const float*)d_in[0];
    const float* xi          = (const float*)d_in[1];
    const float* su          = (const float*)d_in[2];
    const float* si          = (const float*)d_in[3];
    const float* edge_w      = (const float*)d_in[4];
    const float* alpha_logit = (const float*)d_in[5];
    const float* dt          = (const float*)d_in[6];
    const int*   edge_src    = (const int*)d_in[7];
    const int*   edge_dst    = (const int*)d_in[8];
    float*       out         = (float*)d_out;

    const int T = 256;
    const int warpNodeBlocks  = (N_NODES * 32 + T - 1) / T;
    const int eighthNodeBlocks = (N_NODES * 8 + T - 1) / T;   // quarter-warp per node
    const int edgeBlocks      = (N_EDGES + T - 1) / T;
    const int pairBlocks      = (N_NODES * (DIM / 2) + T - 1) / T;

    norm_zero_kernel<<<warpNodeBlocks, T>>>(xu, xi);                  // 1
    count_kernel<<<edgeBlocks, T>>>(edge_dst);                        // 2
    scan_kernel<<<SCAN_NBLOCKS, SCAN_BLOCK>>>();                      // 3
    scatter_kernel<<<edgeBlocks, T>>>(edge_src, edge_dst, edge_w);    // 4
    init_kernel<<<pairBlocks, T>>>(xu, xi, su, si, alpha_logit);      // 5

    void* p_h16 = nullptr; void* p_t16 = nullptr;
    cudaGetSymbolAddress(&p_h16, g_h16);
    cudaGetSymbolAddress(&p_t16, g_t16);
    void* p_h = nullptr;
    cudaGetSymbolAddress(&p_h, g_h);
    const uint2* fh16 = (const uint2*)p_h16;
    uint2*       ft16 = (uint2*)p_t16;
    float4*      fh   = (float4*)p_h;

    for (int step = 0; step < K_STEPS; step++) {
        hop1_kernel<<<eighthNodeBlocks, T>>>(fh16, ft16);
        if (step == K_STEPS - 1) {
            hop2_kernel<true><<<eighthNodeBlocks, T>>>((const uint2*)ft16, (float4*)out, dt);
        } else {
            hop2_kernel<false><<<eighthNodeBlocks, T>>>((const uint2*)ft16, fh, dt);
        }
    }
}